// round 1
// baseline (speedup 1.0000x reference)
#include <cuda_runtime.h>
#include <math.h>

#define NH   12
#define NN   4096
#define ND   128
#define NIN  256

// ---------------- scratch (static device globals; no allocation) ----------------
__device__ float g_QS[NH * NN * ND];
__device__ float g_KS[NH * NN * ND];
__device__ float g_VS[NH * NN * ND];
__device__ float g_QT[NH * NN];
__device__ float g_KT[NH * NN];
__device__ float g_VT[NH * NN];
__device__ float g_OS[NH * NN * ND];   // normalized per-head attention output (s-part)
__device__ float g_OT[NH * NN];        // normalized per-head attention output (t-part)

// =====================================================================
// Kernel 1: hyperbolic linear projections (q, k, v)
//   s = xs @ W^T + b   (per head)          -> g_{Q,K,V}S  [h][n][128]
//   t = sqrt(|s|^2 + 1)                    -> g_{Q,K,V}T  [h][n]
// grid: (NN/64, NH*3), block 256.  Tile: M=64 rows x O=128 cols, K-chunks of 32.
// Thread fragment: 4 rows x 8 cols.
// =====================================================================
__global__ __launch_bounds__(256) void proj_kernel(
    const float* __restrict__ x,
    const float* __restrict__ Wq, const float* __restrict__ bq,
    const float* __restrict__ Wk, const float* __restrict__ bk,
    const float* __restrict__ Wv, const float* __restrict__ bv)
{
    const int by  = blockIdx.y;
    const int h   = by % NH;
    const int sel = by / NH;

    const float* W = (sel == 0) ? Wq : (sel == 1) ? Wk : Wv;
    const float* B = (sel == 0) ? bq : (sel == 1) ? bk : bv;
    float* outS    = (sel == 0) ? g_QS : (sel == 1) ? g_KS : g_VS;
    float* outT    = (sel == 0) ? g_QT : (sel == 1) ? g_KT : g_VT;

    const int n0  = blockIdx.x * 64;
    const int tid = threadIdx.x;
    const int tx  = tid & 15;   // owns output cols tx*8 .. tx*8+7
    const int ty  = tid >> 4;   // owns rows ty*4 .. ty*4+3

    __shared__ float Xt[32][68];    // Xt[k][m]  (xs tile, transposed)
    __shared__ float Wt[32][132];   // Wt[k][o]  (W tile, transposed)

    float acc[4][8];
#pragma unroll
    for (int i = 0; i < 4; i++)
#pragma unroll
        for (int j = 0; j < 8; j++) acc[i][j] = 0.0f;

    const float* Wh = W + (size_t)h * ND * NIN;

    for (int kb = 0; kb < NIN; kb += 32) {
        __syncthreads();
        // load xs tile: rows n0..n0+63, cols kb..kb+31 (xs = x_lorentz[:,1:])
#pragma unroll
        for (int r = 0; r < 8; r++) {
            int idx = tid + r * 256;
            int k = idx & 31, m = idx >> 5;
            Xt[k][m] = x[(size_t)(n0 + m) * 257 + 1 + kb + k];
        }
        // load W tile: rows o 0..127, cols kb..kb+31
#pragma unroll
        for (int r = 0; r < 16; r++) {
            int idx = tid + r * 256;
            int k = idx & 31, o = idx >> 5;
            Wt[k][o] = Wh[(size_t)o * NIN + kb + k];
        }
        __syncthreads();

#pragma unroll
        for (int k = 0; k < 32; k++) {
            float4 a  = *(const float4*)&Xt[k][ty * 4];
            float4 b0 = *(const float4*)&Wt[k][tx * 8];
            float4 b1 = *(const float4*)&Wt[k][tx * 8 + 4];
            float av[4] = {a.x, a.y, a.z, a.w};
            float bv8[8] = {b0.x, b0.y, b0.z, b0.w, b1.x, b1.y, b1.z, b1.w};
#pragma unroll
            for (int i = 0; i < 4; i++)
#pragma unroll
                for (int j = 0; j < 8; j++)
                    acc[i][j] = fmaf(av[i], bv8[j], acc[i][j]);
        }
    }

    // bias + row |s|^2
    float bb[8];
#pragma unroll
    for (int j = 0; j < 8; j++) bb[j] = B[h * ND + tx * 8 + j];

    float ss[4] = {0.f, 0.f, 0.f, 0.f};
#pragma unroll
    for (int i = 0; i < 4; i++)
#pragma unroll
        for (int j = 0; j < 8; j++) {
            acc[i][j] += bb[j];
            ss[i] = fmaf(acc[i][j], acc[i][j], ss[i]);
        }

    // reduce |s|^2 across the 16 tx lanes (xor 8,4,2,1 stays inside 16-lane group)
#pragma unroll
    for (int off = 8; off; off >>= 1)
#pragma unroll
        for (int i = 0; i < 4; i++)
            ss[i] += __shfl_xor_sync(0xffffffffu, ss[i], off);

#pragma unroll
    for (int i = 0; i < 4; i++) {
        int n = n0 + ty * 4 + i;
        float* dst = outS + ((size_t)(h * NN + n)) * ND + tx * 8;
        float4 w0 = {acc[i][0], acc[i][1], acc[i][2], acc[i][3]};
        float4 w1 = {acc[i][4], acc[i][5], acc[i][6], acc[i][7]};
        *(float4*)(dst)     = w0;
        *(float4*)(dst + 4) = w1;
        if (tx == 0) outT[h * NN + n] = sqrtf(ss[i] + 1.0f);
    }
}

// =====================================================================
// Kernel 2: flash attention + first midpoint_norm.
// grid: (NN/64, NH), block 256, dynamic smem.
// Q tile 64 rows; stream over 64-key tiles; online softmax.
// Score dot is a 129-dim dot: dim 0 carries (-t_q) * (t_k).
// Epilogue: ave = acc/l ; midpoint_norm -> g_OS/g_OT.
// =====================================================================
#define ATTN_SMEM_FLOATS (129*68 + 129*68 + 64*68 + 64*128 + 64)
#define ATTN_SMEM_BYTES  (ATTN_SMEM_FLOATS * 4)

__global__ __launch_bounds__(256, 1) void attn_kernel(const float* __restrict__ scale_ptr)
{
    extern __shared__ float sm[];
    float* Qt = sm;                       // [129][68]  (row 0 = -t_q)
    float* Kt = sm + 129 * 68;            // [129][68]  (row 0 = +t_k)
    float* Pm = sm + 2 * 129 * 68;        // [64][68]
    float* Vs = Pm + 64 * 68;             // [64][128]
    float* vt = Vs + 64 * 128;            // [64]

    const int h   = blockIdx.y;
    const int m0  = blockIdx.x * 64;
    const int tid = threadIdx.x;
    const int tx  = tid & 15;             // score cols tx*4.. / PV cols tx*8..
    const int ty  = tid >> 4;             // rows ty*4..ty*4+3 (same in both layouts)

    const float alpha = 2.0f / scale_ptr[0];

    // load Q tile (transposed, with sign-folded t in row 0)
    for (int idx = tid; idx < 64 * 129; idx += 256) {
        int m = idx / 129;
        int d = idx - m * 129;
        float v = (d == 0) ? -g_QT[h * NN + m0 + m]
                           :  g_QS[((size_t)(h * NN + m0 + m)) * ND + d - 1];
        Qt[d * 68 + m] = v;
    }

    float m_i[4], l_i[4], acc_t[4], acc[4][8];
#pragma unroll
    for (int i = 0; i < 4; i++) {
        m_i[i] = -INFINITY; l_i[i] = 0.f; acc_t[i] = 0.f;
#pragma unroll
        for (int j = 0; j < 8; j++) acc[i][j] = 0.f;
    }

    for (int k0 = 0; k0 < NN; k0 += 64) {
        __syncthreads();   // previous PV done before overwriting K/V
        for (int idx = tid; idx < 64 * 129; idx += 256) {
            int n = idx / 129;
            int d = idx - n * 129;
            float v = (d == 0) ? g_KT[h * NN + k0 + n]
                               : g_KS[((size_t)(h * NN + k0 + n)) * ND + d - 1];
            Kt[d * 68 + n] = v;
        }
#pragma unroll
        for (int r = 0; r < 8; r++) {                 // 64*128/4 float4 = 2048 / 256
            int idx = tid + r * 256;
            int n  = idx >> 5;
            int d4 = (idx & 31) * 4;
            *(float4*)&Vs[n * 128 + d4] =
                *(const float4*)&g_VS[((size_t)(h * NN + k0 + n)) * ND + d4];
        }
        if (tid < 64) vt[tid] = g_VT[h * NN + k0 + tid];
        __syncthreads();

        // ---- scores: 4x4 fragment over 129 dims ----
        float s[4][4];
#pragma unroll
        for (int i = 0; i < 4; i++)
#pragma unroll
            for (int j = 0; j < 4; j++) s[i][j] = 0.f;

        const float* qp = Qt + ty * 4;
        const float* kp = Kt + tx * 4;
        for (int d = 0; d < 129; d++) {
            float4 a = *(const float4*)qp; qp += 68;
            float4 b = *(const float4*)kp; kp += 68;
            float av[4] = {a.x, a.y, a.z, a.w};
            float bv4[4] = {b.x, b.y, b.z, b.w};
#pragma unroll
            for (int i = 0; i < 4; i++)
#pragma unroll
                for (int j = 0; j < 4; j++)
                    s[i][j] = fmaf(av[i], bv4[j], s[i][j]);
        }
#pragma unroll
        for (int i = 0; i < 4; i++)
#pragma unroll
            for (int j = 0; j < 4; j++) s[i][j] *= alpha;

        // ---- online softmax (row stats across 16 tx lanes) ----
        float tmax[4];
#pragma unroll
        for (int i = 0; i < 4; i++)
            tmax[i] = fmaxf(fmaxf(s[i][0], s[i][1]), fmaxf(s[i][2], s[i][3]));
#pragma unroll
        for (int off = 8; off; off >>= 1)
#pragma unroll
            for (int i = 0; i < 4; i++)
                tmax[i] = fmaxf(tmax[i], __shfl_xor_sync(0xffffffffu, tmax[i], off));

        float fac[4], tsum[4];
#pragma unroll
        for (int i = 0; i < 4; i++) {
            float newm = fmaxf(m_i[i], tmax[i]);
            fac[i] = __expf(m_i[i] - newm);
            m_i[i] = newm;
            tsum[i] = 0.f;
#pragma unroll
            for (int j = 0; j < 4; j++) {
                s[i][j] = __expf(s[i][j] - newm);
                tsum[i] += s[i][j];
            }
        }
#pragma unroll
        for (int off = 8; off; off >>= 1)
#pragma unroll
            for (int i = 0; i < 4; i++)
                tsum[i] += __shfl_xor_sync(0xffffffffu, tsum[i], off);

#pragma unroll
        for (int i = 0; i < 4; i++) {
            l_i[i] = l_i[i] * fac[i] + tsum[i];
            acc_t[i] *= fac[i];
#pragma unroll
            for (int j = 0; j < 8; j++) acc[i][j] *= fac[i];
        }

        // stage P tile
#pragma unroll
        for (int i = 0; i < 4; i++)
#pragma unroll
            for (int j = 0; j < 4; j++)
                Pm[(ty * 4 + i) * 68 + tx * 4 + j] = s[i][j];
        __syncthreads();

        // ---- PV: acc[4][8] += P(64) * V ----
#pragma unroll 4
        for (int k = 0; k < 64; k++) {
            float p[4];
#pragma unroll
            for (int i = 0; i < 4; i++) p[i] = Pm[(ty * 4 + i) * 68 + k];
            float4 vA = *(const float4*)&Vs[k * 128 + tx * 8];
            float4 vB = *(const float4*)&Vs[k * 128 + tx * 8 + 4];
            float va[8] = {vA.x, vA.y, vA.z, vA.w, vB.x, vB.y, vB.z, vB.w};
#pragma unroll
            for (int i = 0; i < 4; i++)
#pragma unroll
                for (int j = 0; j < 8; j++)
                    acc[i][j] = fmaf(p[i], va[j], acc[i][j]);
            if (tx == 0) {
                float vv = vt[k];
#pragma unroll
                for (int i = 0; i < 4; i++) acc_t[i] = fmaf(p[i], vv, acc_t[i]);
            }
        }
    }

    // ---- epilogue: ave = acc/l, midpoint_norm, store ----
    float ssum[4];
#pragma unroll
    for (int i = 0; i < 4; i++) {
        float rl = 1.0f / l_i[i];
        ssum[i] = 0.f;
#pragma unroll
        for (int j = 0; j < 8; j++) {
            acc[i][j] *= rl;
            ssum[i] = fmaf(acc[i][j], acc[i][j], ssum[i]);
        }
        acc_t[i] *= rl;   // valid on tx==0 only
    }
#pragma unroll
    for (int off = 8; off; off >>= 1)
#pragma unroll
        for (int i = 0; i < 4; i++)
            ssum[i] += __shfl_xor_sync(0xffffffffu, ssum[i], off);

    const int src = (tid & 31) & 16;   // lane holding tx==0 of this 16-group
#pragma unroll
    for (int i = 0; i < 4; i++) {
        float inner = ssum[i] - acc_t[i] * acc_t[i];           // correct on tx==0
        float f = 1.0f / sqrtf(fmaxf(fabsf(inner), 1e-8f));
        f = __shfl_sync(0xffffffffu, f, src, 32);              // broadcast tx==0 value
        int n = m0 + ty * 4 + i;
        float* dst = g_OS + ((size_t)(h * NN + n)) * ND + tx * 8;
        float4 w0 = {acc[i][0] * f, acc[i][1] * f, acc[i][2] * f, acc[i][3] * f};
        float4 w1 = {acc[i][4] * f, acc[i][5] * f, acc[i][6] * f, acc[i][7] * f};
        *(float4*)(dst)     = w0;
        *(float4*)(dst + 4) = w1;
        if (tx == 0) g_OT[h * NN + n] = acc_t[i] * f;
    }
}

// =====================================================================
// Kernel 3: head mean + final midpoint_norm -> out[n][129]
// One warp per n; lane owns 4 s-dims.
// =====================================================================
__global__ __launch_bounds__(256) void final_kernel(float* __restrict__ out)
{
    const int warp = threadIdx.x >> 5;
    const int lane = threadIdx.x & 31;
    const int n = blockIdx.x * 8 + warp;

    float s0 = 0.f, s1 = 0.f, s2 = 0.f, s3 = 0.f, t = 0.f;
#pragma unroll
    for (int h = 0; h < NH; h++) {
        float4 v = *(const float4*)&g_OS[((size_t)(h * NN + n)) * ND + lane * 4];
        s0 += v.x; s1 += v.y; s2 += v.z; s3 += v.w;
        t += g_OT[h * NN + n];
    }
    const float inv = 1.0f / (float)NH;
    s0 *= inv; s1 *= inv; s2 *= inv; s3 *= inv; t *= inv;

    float q = s0 * s0 + s1 * s1 + s2 * s2 + s3 * s3;
#pragma unroll
    for (int off = 16; off; off >>= 1) q += __shfl_xor_sync(0xffffffffu, q, off);

    float inner = q - t * t;
    float f = 1.0f / sqrtf(fmaxf(fabsf(inner), 1e-8f));

    float* o = out + (size_t)n * 129;
    if (lane == 0) o[0] = t * f;
    o[1 + lane * 4 + 0] = s0 * f;
    o[1 + lane * 4 + 1] = s1 * f;
    o[1 + lane * 4 + 2] = s2 * f;
    o[1 + lane * 4 + 3] = s3 * f;
}

// =====================================================================
extern "C" void kernel_launch(void* const* d_in, const int* in_sizes, int n_in,
                              void* d_out, int out_size)
{
    const float* x     = (const float*)d_in[0];
    const float* Wq    = (const float*)d_in[1];
    const float* bq    = (const float*)d_in[2];
    const float* Wk    = (const float*)d_in[3];
    const float* bk    = (const float*)d_in[4];
    const float* Wv    = (const float*)d_in[5];
    const float* bv    = (const float*)d_in[6];
    const float* scale = (const float*)d_in[7];
    float* out = (float*)d_out;

    cudaFuncSetAttribute(attn_kernel,
                         cudaFuncAttributeMaxDynamicSharedMemorySize,
                         ATTN_SMEM_BYTES);

    proj_kernel<<<dim3(NN / 64, NH * 3), 256>>>(x, Wq, bq, Wk, bk, Wv, bv);
    attn_kernel<<<dim3(NN / 64, NH), 256, ATTN_SMEM_BYTES>>>(scale);
    final_kernel<<<NN / 8, 256>>>(out);
}

// round 2
// speedup vs baseline: 1.1200x; 1.1200x over previous
#include <cuda_runtime.h>
#include <math.h>

#define NH   12
#define NN   4096
#define ND   128
#define NIN  256

typedef unsigned long long u64t;

// ---- packed f32x2 helpers (FFMA2 path — only reachable via PTX) ----
__device__ __forceinline__ u64t pk2(float lo, float hi) {
    u64t r;
    asm("mov.b64 %0, {%1, %2};" : "=l"(r) : "f"(lo), "f"(hi));
    return r;
}
__device__ __forceinline__ void upk2(u64t v, float& lo, float& hi) {
    asm("mov.b64 {%0, %1}, %2;" : "=f"(lo), "=f"(hi) : "l"(v));
}
__device__ __forceinline__ void fma2(u64t& d, u64t a, u64t b) {
    asm("fma.rn.f32x2 %0, %1, %2, %0;" : "+l"(d) : "l"(a), "l"(b));
}
__device__ __forceinline__ void mul2(u64t& d, u64t a) {
    asm("mul.rn.f32x2 %0, %0, %1;" : "+l"(d) : "l"(a));
}

// ---------------- scratch (static device globals; no allocation) ----------------
__device__ float g_QS[NH * NN * ND];
__device__ float g_KS[NH * NN * ND];
__device__ float g_VS[NH * NN * ND];
__device__ float g_QT[NH * NN];
__device__ float g_KT[NH * NN];
__device__ float g_VT[NH * NN];
__device__ float g_OS[NH * NN * ND];
__device__ float g_OT[NH * NN];

// =====================================================================
// Kernel 1: hyperbolic linear projections (q, k, v) — FFMA2 inner loop
// =====================================================================
__global__ __launch_bounds__(256) void proj_kernel(
    const float* __restrict__ x,
    const float* __restrict__ Wq, const float* __restrict__ bq,
    const float* __restrict__ Wk, const float* __restrict__ bk,
    const float* __restrict__ Wv, const float* __restrict__ bv)
{
    const int by  = blockIdx.y;
    const int h   = by % NH;
    const int sel = by / NH;

    const float* W = (sel == 0) ? Wq : (sel == 1) ? Wk : Wv;
    const float* B = (sel == 0) ? bq : (sel == 1) ? bk : bv;
    float* outS    = (sel == 0) ? g_QS : (sel == 1) ? g_KS : g_VS;
    float* outT    = (sel == 0) ? g_QT : (sel == 1) ? g_KT : g_VT;

    const int n0  = blockIdx.x * 64;
    const int tid = threadIdx.x;
    const int tx  = tid & 15;
    const int ty  = tid >> 4;

    __shared__ float Xt[32][68];
    __shared__ float Wt[32][132];

    u64t accp[4][4];
#pragma unroll
    for (int i = 0; i < 4; i++)
#pragma unroll
        for (int j = 0; j < 4; j++) accp[i][j] = 0ull;

    const float* Wh = W + (size_t)h * ND * NIN;

    for (int kb = 0; kb < NIN; kb += 32) {
        __syncthreads();
#pragma unroll
        for (int r = 0; r < 8; r++) {
            int idx = tid + r * 256;
            int k = idx & 31, m = idx >> 5;
            Xt[k][m] = x[(size_t)(n0 + m) * 257 + 1 + kb + k];
        }
#pragma unroll
        for (int r = 0; r < 16; r++) {
            int idx = tid + r * 256;
            int k = idx & 31, o = idx >> 5;
            Wt[k][o] = Wh[(size_t)o * NIN + kb + k];
        }
        __syncthreads();

#pragma unroll
        for (int k = 0; k < 32; k++) {
            float4 a  = *(const float4*)&Xt[k][ty * 4];
            float4 b0 = *(const float4*)&Wt[k][tx * 8];
            float4 b1 = *(const float4*)&Wt[k][tx * 8 + 4];
            u64t bp[4] = {pk2(b0.x, b0.y), pk2(b0.z, b0.w),
                          pk2(b1.x, b1.y), pk2(b1.z, b1.w)};
            float av[4] = {a.x, a.y, a.z, a.w};
#pragma unroll
            for (int i = 0; i < 4; i++) {
                u64t ap = pk2(av[i], av[i]);
#pragma unroll
                for (int j = 0; j < 4; j++) fma2(accp[i][j], ap, bp[j]);
            }
        }
    }

    float acc[4][8];
#pragma unroll
    for (int i = 0; i < 4; i++)
#pragma unroll
        for (int j = 0; j < 4; j++) upk2(accp[i][j], acc[i][j * 2], acc[i][j * 2 + 1]);

    float bb[8];
#pragma unroll
    for (int j = 0; j < 8; j++) bb[j] = B[h * ND + tx * 8 + j];

    float ss[4] = {0.f, 0.f, 0.f, 0.f};
#pragma unroll
    for (int i = 0; i < 4; i++)
#pragma unroll
        for (int j = 0; j < 8; j++) {
            acc[i][j] += bb[j];
            ss[i] = fmaf(acc[i][j], acc[i][j], ss[i]);
        }

#pragma unroll
    for (int off = 8; off; off >>= 1)
#pragma unroll
        for (int i = 0; i < 4; i++)
            ss[i] += __shfl_xor_sync(0xffffffffu, ss[i], off);

#pragma unroll
    for (int i = 0; i < 4; i++) {
        int n = n0 + ty * 4 + i;
        float* dst = outS + ((size_t)(h * NN + n)) * ND + tx * 8;
        float4 w0 = {acc[i][0], acc[i][1], acc[i][2], acc[i][3]};
        float4 w1 = {acc[i][4], acc[i][5], acc[i][6], acc[i][7]};
        *(float4*)(dst)     = w0;
        *(float4*)(dst + 4) = w1;
        if (tx == 0) outT[h * NN + n] = sqrtf(ss[i] + 1.0f);
    }
}

// =====================================================================
// Kernel 2: flash attention + first midpoint_norm — FFMA2 score/PV loops
// =====================================================================
#define ATTN_SMEM_FLOATS (129*68 + 129*68 + 64*68 + 64*128 + 64)
#define ATTN_SMEM_BYTES  (ATTN_SMEM_FLOATS * 4)

__global__ __launch_bounds__(256, 1) void attn_kernel(const float* __restrict__ scale_ptr)
{
    extern __shared__ float sm[];
    float* Qt = sm;                       // [129][68]  (row 0 = -t_q)
    float* Kt = sm + 129 * 68;            // [129][68]  (row 0 = +t_k)
    float* Pm = sm + 2 * 129 * 68;        // [64][68]
    float* Vs = Pm + 64 * 68;             // [64][128]
    float* vt = Vs + 64 * 128;            // [64]

    const int h   = blockIdx.y;
    const int m0  = blockIdx.x * 64;
    const int tid = threadIdx.x;
    const int tx  = tid & 15;
    const int ty  = tid >> 4;

    const float alpha = 2.0f / scale_ptr[0];

    for (int idx = tid; idx < 64 * 129; idx += 256) {
        int m = idx / 129;
        int d = idx - m * 129;
        float v = (d == 0) ? -g_QT[h * NN + m0 + m]
                           :  g_QS[((size_t)(h * NN + m0 + m)) * ND + d - 1];
        Qt[d * 68 + m] = v;
    }

    float m_i[4], l_i[4], acc_t[4];
    u64t accp[4][4];
#pragma unroll
    for (int i = 0; i < 4; i++) {
        m_i[i] = -INFINITY; l_i[i] = 0.f; acc_t[i] = 0.f;
#pragma unroll
        for (int j = 0; j < 4; j++) accp[i][j] = 0ull;
    }

    for (int k0 = 0; k0 < NN; k0 += 64) {
        __syncthreads();
        for (int idx = tid; idx < 64 * 129; idx += 256) {
            int n = idx / 129;
            int d = idx - n * 129;
            float v = (d == 0) ? g_KT[h * NN + k0 + n]
                               : g_KS[((size_t)(h * NN + k0 + n)) * ND + d - 1];
            Kt[d * 68 + n] = v;
        }
#pragma unroll
        for (int r = 0; r < 8; r++) {
            int idx = tid + r * 256;
            int n  = idx >> 5;
            int d4 = (idx & 31) * 4;
            *(float4*)&Vs[n * 128 + d4] =
                *(const float4*)&g_VS[((size_t)(h * NN + k0 + n)) * ND + d4];
        }
        if (tid < 64) vt[tid] = g_VT[h * NN + k0 + tid];
        __syncthreads();

        // ---- scores: packed 4x(2x f32x2) fragment over 129 dims ----
        u64t sp[4][2];
#pragma unroll
        for (int i = 0; i < 4; i++) { sp[i][0] = 0ull; sp[i][1] = 0ull; }

        const float* qp = Qt + ty * 4;
        const float* kp = Kt + tx * 4;
        for (int d = 0; d < 129; d++) {
            float4 a = *(const float4*)qp; qp += 68;
            float4 b = *(const float4*)kp; kp += 68;
            u64t bp0 = pk2(b.x, b.y);
            u64t bp1 = pk2(b.z, b.w);
            float av[4] = {a.x, a.y, a.z, a.w};
#pragma unroll
            for (int i = 0; i < 4; i++) {
                u64t ap = pk2(av[i], av[i]);
                fma2(sp[i][0], ap, bp0);
                fma2(sp[i][1], ap, bp1);
            }
        }

        float s[4][4];
#pragma unroll
        for (int i = 0; i < 4; i++) {
            upk2(sp[i][0], s[i][0], s[i][1]);
            upk2(sp[i][1], s[i][2], s[i][3]);
#pragma unroll
            for (int j = 0; j < 4; j++) s[i][j] *= alpha;
        }

        // ---- online softmax ----
        float tmax[4];
#pragma unroll
        for (int i = 0; i < 4; i++)
            tmax[i] = fmaxf(fmaxf(s[i][0], s[i][1]), fmaxf(s[i][2], s[i][3]));
#pragma unroll
        for (int off = 8; off; off >>= 1)
#pragma unroll
            for (int i = 0; i < 4; i++)
                tmax[i] = fmaxf(tmax[i], __shfl_xor_sync(0xffffffffu, tmax[i], off));

        float fac[4], tsum[4];
#pragma unroll
        for (int i = 0; i < 4; i++) {
            float newm = fmaxf(m_i[i], tmax[i]);
            fac[i] = __expf(m_i[i] - newm);
            m_i[i] = newm;
            tsum[i] = 0.f;
#pragma unroll
            for (int j = 0; j < 4; j++) {
                s[i][j] = __expf(s[i][j] - newm);
                tsum[i] += s[i][j];
            }
        }
#pragma unroll
        for (int off = 8; off; off >>= 1)
#pragma unroll
            for (int i = 0; i < 4; i++)
                tsum[i] += __shfl_xor_sync(0xffffffffu, tsum[i], off);

#pragma unroll
        for (int i = 0; i < 4; i++) {
            l_i[i] = l_i[i] * fac[i] + tsum[i];
            acc_t[i] *= fac[i];
            u64t fp = pk2(fac[i], fac[i]);
#pragma unroll
            for (int j = 0; j < 4; j++) mul2(accp[i][j], fp);
        }

#pragma unroll
        for (int i = 0; i < 4; i++)
#pragma unroll
            for (int j = 0; j < 4; j++)
                Pm[(ty * 4 + i) * 68 + tx * 4 + j] = s[i][j];
        __syncthreads();

        // ---- PV: packed acc[4][4x f32x2] += P(64) * V ----
#pragma unroll 4
        for (int k = 0; k < 64; k++) {
            float p[4];
#pragma unroll
            for (int i = 0; i < 4; i++) p[i] = Pm[(ty * 4 + i) * 68 + k];
            float4 vA = *(const float4*)&Vs[k * 128 + tx * 8];
            float4 vB = *(const float4*)&Vs[k * 128 + tx * 8 + 4];
            u64t vp[4] = {pk2(vA.x, vA.y), pk2(vA.z, vA.w),
                          pk2(vB.x, vB.y), pk2(vB.z, vB.w)};
#pragma unroll
            for (int i = 0; i < 4; i++) {
                u64t pp = pk2(p[i], p[i]);
#pragma unroll
                for (int j = 0; j < 4; j++) fma2(accp[i][j], pp, vp[j]);
            }
            if (tx == 0) {
                float vv = vt[k];
#pragma unroll
                for (int i = 0; i < 4; i++) acc_t[i] = fmaf(p[i], vv, acc_t[i]);
            }
        }
    }

    // ---- epilogue: ave = acc/l, midpoint_norm, store ----
    float acc[4][8];
#pragma unroll
    for (int i = 0; i < 4; i++)
#pragma unroll
        for (int j = 0; j < 4; j++) upk2(accp[i][j], acc[i][j * 2], acc[i][j * 2 + 1]);

    float ssum[4];
#pragma unroll
    for (int i = 0; i < 4; i++) {
        float rl = 1.0f / l_i[i];
        ssum[i] = 0.f;
#pragma unroll
        for (int j = 0; j < 8; j++) {
            acc[i][j] *= rl;
            ssum[i] = fmaf(acc[i][j], acc[i][j], ssum[i]);
        }
        acc_t[i] *= rl;
    }
#pragma unroll
    for (int off = 8; off; off >>= 1)
#pragma unroll
        for (int i = 0; i < 4; i++)
            ssum[i] += __shfl_xor_sync(0xffffffffu, ssum[i], off);

    const int src = (tid & 31) & 16;
#pragma unroll
    for (int i = 0; i < 4; i++) {
        float inner = ssum[i] - acc_t[i] * acc_t[i];
        float f = 1.0f / sqrtf(fmaxf(fabsf(inner), 1e-8f));
        f = __shfl_sync(0xffffffffu, f, src, 32);
        int n = m0 + ty * 4 + i;
        float* dst = g_OS + ((size_t)(h * NN + n)) * ND + tx * 8;
        float4 w0 = {acc[i][0] * f, acc[i][1] * f, acc[i][2] * f, acc[i][3] * f};
        float4 w1 = {acc[i][4] * f, acc[i][5] * f, acc[i][6] * f, acc[i][7] * f};
        *(float4*)(dst)     = w0;
        *(float4*)(dst + 4) = w1;
        if (tx == 0) g_OT[h * NN + n] = acc_t[i] * f;
    }
}

// =====================================================================
// Kernel 3: head mean + final midpoint_norm -> out[n][129]
// =====================================================================
__global__ __launch_bounds__(256) void final_kernel(float* __restrict__ out)
{
    const int warp = threadIdx.x >> 5;
    const int lane = threadIdx.x & 31;
    const int n = blockIdx.x * 8 + warp;

    float s0 = 0.f, s1 = 0.f, s2 = 0.f, s3 = 0.f, t = 0.f;
#pragma unroll
    for (int h = 0; h < NH; h++) {
        float4 v = *(const float4*)&g_OS[((size_t)(h * NN + n)) * ND + lane * 4];
        s0 += v.x; s1 += v.y; s2 += v.z; s3 += v.w;
        t += g_OT[h * NN + n];
    }
    const float inv = 1.0f / (float)NH;
    s0 *= inv; s1 *= inv; s2 *= inv; s3 *= inv; t *= inv;

    float q = s0 * s0 + s1 * s1 + s2 * s2 + s3 * s3;
#pragma unroll
    for (int off = 16; off; off >>= 1) q += __shfl_xor_sync(0xffffffffu, q, off);

    float inner = q - t * t;
    float f = 1.0f / sqrtf(fmaxf(fabsf(inner), 1e-8f));

    float* o = out + (size_t)n * 129;
    if (lane == 0) o[0] = t * f;
    o[1 + lane * 4 + 0] = s0 * f;
    o[1 + lane * 4 + 1] = s1 * f;
    o[1 + lane * 4 + 2] = s2 * f;
    o[1 + lane * 4 + 3] = s3 * f;
}

// =====================================================================
extern "C" void kernel_launch(void* const* d_in, const int* in_sizes, int n_in,
                              void* d_out, int out_size)
{
    const float* x     = (const float*)d_in[0];
    const float* Wq    = (const float*)d_in[1];
    const float* bq    = (const float*)d_in[2];
    const float* Wk    = (const float*)d_in[3];
    const float* bk    = (const float*)d_in[4];
    const float* Wv    = (const float*)d_in[5];
    const float* bv    = (const float*)d_in[6];
    const float* scale = (const float*)d_in[7];
    float* out = (float*)d_out;

    cudaFuncSetAttribute(attn_kernel,
                         cudaFuncAttributeMaxDynamicSharedMemorySize,
                         ATTN_SMEM_BYTES);

    proj_kernel<<<dim3(NN / 64, NH * 3), 256>>>(x, Wq, bq, Wk, bk, Wv, bv);
    attn_kernel<<<dim3(NN / 64, NH), 256, ATTN_SMEM_BYTES>>>(scale);
    final_kernel<<<NN / 8, 256>>>(out);
}